// round 14
// baseline (speedup 1.0000x reference)
#include <cuda_runtime.h>
#include <cuda_bf16.h>
#include <cuda_fp16.h>
#include <cstdint>

// ============================================================================
// spectralNNDeepshared2 — Round 13:
//   1-term single-fp16 mma.sync everywhere (HMMA-count ceiling confirmed
//   R8/R11; measured incoherent error accumulation allows dropping all
//   residual digits). Executed FLOP = logical FLOP = 65G.
// ============================================================================

// ---------------- scratch ----------------
__device__ __half g_uT16[64 * 1024];
__device__ __half g_W016[64 * 256 * 64];
__device__ __half g_W16[3L * 64 * 256 * 256];
__device__ __half g_Wf16[64 * 65 * 256];
__device__ __half g_actA16[64L * 256 * 1024];
__device__ __half g_actB16[64L * 256 * 1024];
__device__ __half g_A16[4096L * 4160];
__device__ __half g_G16[4160L * 1024];

__device__ __forceinline__ float sigmoidf_fast(float x) {
    return 1.0f / (1.0f + __expf(-x));
}
__device__ __forceinline__ uint32_t smem_u32(const void* p) {
    uint32_t a;
    asm("{ .reg .u64 t; cvta.to.shared.u64 t, %1; cvt.u32.u64 %0, t; }"
        : "=r"(a) : "l"(p));
    return a;
}

// ---------------- cp.async / ldmatrix / mma helpers ----------------
__device__ __forceinline__ void cp16(uint32_t dst, const void* src) {
    asm volatile("cp.async.cg.shared.global [%0], [%1], 16;\n"
                 :: "r"(dst), "l"(src));
}
__device__ __forceinline__ void cp16z(uint32_t dst, const void* src, bool valid) {
    int sz = valid ? 16 : 0;
    asm volatile("cp.async.cg.shared.global [%0], [%1], 16, %2;\n"
                 :: "r"(dst), "l"(src), "r"(sz));
}
#define CP_COMMIT() asm volatile("cp.async.commit_group;\n" ::: "memory")
#define CP_WAIT(n)  asm volatile("cp.async.wait_group %0;\n" :: "n"(n) : "memory")

__device__ __forceinline__ void ldsm_x4(uint32_t* r, uint32_t addr) {
    asm volatile("ldmatrix.sync.aligned.m8n8.x4.shared.b16 {%0,%1,%2,%3}, [%4];"
        : "=r"(r[0]), "=r"(r[1]), "=r"(r[2]), "=r"(r[3]) : "r"(addr));
}
__device__ __forceinline__ void ldsm_x4t(uint32_t* r, uint32_t addr) {
    asm volatile("ldmatrix.sync.aligned.m8n8.x4.trans.shared.b16 {%0,%1,%2,%3}, [%4];"
        : "=r"(r[0]), "=r"(r[1]), "=r"(r[2]), "=r"(r[3]) : "r"(addr));
}
__device__ __forceinline__ void mma_f16(float* d, const uint32_t* a, const uint32_t* b) {
    asm volatile(
        "mma.sync.aligned.m16n8k16.row.col.f32.f16.f16.f32 "
        "{%0,%1,%2,%3}, {%4,%5,%6,%7}, {%8,%9}, {%0,%1,%2,%3};"
        : "+f"(d[0]), "+f"(d[1]), "+f"(d[2]), "+f"(d[3])
        : "r"(a[0]), "r"(a[1]), "r"(a[2]), "r"(a[3]), "r"(b[0]), "r"(b[1]));
}

// ============================================================================
// Precompute kernels
// ============================================================================
// fp32 -> single fp16 convert
__global__ void cvt16_kernel(const float* __restrict__ src,
                             __half* __restrict__ dst, long count)
{
    long i = (long)blockIdx.x * 1024 + threadIdx.x * 4;
    if (i + 3 >= count) {
        for (long k = i; k < count; k++) dst[k] = __float2half_rn(src[k]);
        return;
    }
    float4 v4 = *reinterpret_cast<const float4*>(src + i);
    __half h4[4];
    h4[0] = __float2half_rn(v4.x);
    h4[1] = __float2half_rn(v4.y);
    h4[2] = __float2half_rn(v4.z);
    h4[3] = __float2half_rn(v4.w);
    *reinterpret_cast<uint2*>(dst + i) = *reinterpret_cast<uint2*>(h4);
}

// Transpose u (1024x64) -> uT (64x1024) single fp16
__global__ void transpose_u16_kernel(const float* __restrict__ u,
                                     __half* __restrict__ uT)
{
    __shared__ float t[32][33];
    int b0 = blockIdx.x * 32;
    int d0 = blockIdx.y * 32;
    int x = threadIdx.x, y = threadIdx.y;
    t[y][x] = u[(long)(b0 + y) * 64 + (d0 + x)];
    __syncthreads();
    uT[(long)(d0 + y) * 1024 + (b0 + x)] = __float2half_rn(t[x][y]);
}

// Sliding-window A (4096 x 4160) single fp16
__global__ void build_A16_kernel(const float* __restrict__ xi,
                                 __half* __restrict__ A)
{
    int n = blockIdx.x;
    for (int k = threadIdx.x; k < 4160; k += 256) {
        int m = k / 65;
        int j = k - m * 65;
        A[(long)n * 4160 + k] = __float2half_rn(xi[m * 4160 + n + j]);
    }
}

// ============================================================================
// Shared smem layout: A (128x32) + B (32x128), single fp16, 3-stage ring
// ============================================================================
#define ASTRIDE 80
#define BSTRIDE 272
#define A_TILE  (128 * ASTRIDE)             // 10240
#define B_TILE  (32 * BSTRIDE)              // 8704
#define STAGE   (A_TILE + B_TILE)           // 18944
#define NSTAGES 3
#define SMEM_TOTAL (NSTAGES * STAGE)        // 56832
#define O_A 0
#define O_B A_TILE

// ============================================================================
// MLP layer: Y[m] = sigmoid(W[m] (rows x K) @ X[m] (K x 1024) + bias[m])
// single fp16 1-term. Writes single-fp16 activations.
// ============================================================================
__global__ __launch_bounds__(256, 2) void mlp_mma_kernel(
    const __half* __restrict__ W, long wStride,
    const __half* __restrict__ X, long xStride,
    const float* __restrict__ bias_all, int biasStride,
    __half* __restrict__ Y, long yStride,
    int rows, int K)
{
    extern __shared__ char smem[];
    const uint32_t sb = smem_u32(smem);
    const int tid = threadIdx.x;
    const int lane = tid & 31;
    const int wid = tid >> 5;
    const int wm = wid & 3;
    const int wn = wid >> 2;
    const int m = blockIdx.z;
    const int row0 = blockIdx.y * 128;
    const int col0 = blockIdx.x * 128;

    const __half* Aw = W + (long)m * wStride;
    const __half* Bx = X + (long)m * xStride;
    const float* bias = bias_all + (long)m * biasStride;

    float acc[2][8][4];
    #pragma unroll
    for (int mi = 0; mi < 2; mi++)
        #pragma unroll
        for (int nj = 0; nj < 8; nj++)
            #pragma unroll
            for (int q = 0; q < 4; q++) acc[mi][nj][q] = 0.0f;

    const int quad = lane >> 3;
    const int r8 = lane & 7;
    const uint32_t aoff = (wm * 32 + (quad & 1) * 8 + r8) * ASTRIDE + (quad >> 1) * 16;
    const uint32_t boff = ((quad & 1) * 8 + r8) * BSTRIDE + (wn * 64 + (quad >> 1) * 8) * 2;

    const int nChunks = K >> 5;

    auto load = [&](int stageIdx, int k0) {
        uint32_t sbase = sb + (uint32_t)stageIdx * STAGE;
        {
            int r = tid >> 1;
            int c = tid & 1;
            int gr = row0 + r;
            bool ok = gr < rows;
            long g = (long)(ok ? gr : 0) * K + k0 + c * 8;
            cp16z(sbase + O_A + r * ASTRIDE + c * 16 + (tid & 1) * 0, Aw + g, ok);
            // second half of the 32-wide row
            long g2 = g + 16;
            cp16z(sbase + O_A + r * ASTRIDE + c * 16 + 32, Aw + g2, ok);
        }
        #pragma unroll
        for (int i = 0; i < 2; i++) {
            int idx = tid + i * 256;
            int r = idx >> 4;
            int c = idx & 15;
            long g = (long)(k0 + r) * 1024 + col0 + c * 8;
            cp16(sbase + O_B + r * BSTRIDE + c * 16, Bx + g);
        }
    };

    load(0, 0);
    CP_COMMIT();
    if (nChunks > 1) load(1, 32);
    CP_COMMIT();

    int curStage = 0, nxtStage = 2;
    for (int t = 0; t < nChunks; t++) {
        CP_WAIT(1);
        __syncthreads();
        if (t + 2 < nChunks) load(nxtStage, (t + 2) * 32);
        CP_COMMIT();

        const uint32_t cur = sb + (uint32_t)curStage * STAGE;
        curStage = (curStage == NSTAGES - 1) ? 0 : curStage + 1;
        nxtStage = (nxtStage == NSTAGES - 1) ? 0 : nxtStage + 1;

        #pragma unroll
        for (int ks = 0; ks < 2; ks++) {
            uint32_t af[2][4];
            ldsm_x4(af[0], cur + O_A + aoff + ks * 32);
            ldsm_x4(af[1], cur + O_A + aoff + 16 * ASTRIDE + ks * 32);

            #pragma unroll
            for (int g = 0; g < 4; g++) {
                uint32_t rh[4];
                ldsm_x4t(rh, cur + O_B + boff + g * 32 + ks * 16 * BSTRIDE);
                mma_f16(acc[0][2 * g],     af[0], &rh[0]);
                mma_f16(acc[0][2 * g + 1], af[0], &rh[2]);
                mma_f16(acc[1][2 * g],     af[1], &rh[0]);
                mma_f16(acc[1][2 * g + 1], af[1], &rh[2]);
            }
        }
        __syncthreads();
    }

    // epilogue: bias + sigmoid -> single fp16
    const int grp = lane >> 2;
    const int qid = lane & 3;
    __half* y = Y + (long)m * yStride;
    #pragma unroll
    for (int mi = 0; mi < 2; mi++) {
        int rbase = row0 + wm * 32 + mi * 16;
        #pragma unroll
        for (int half = 0; half < 2; half++) {
            int gr = rbase + grp + half * 8;
            if (gr >= rows) continue;
            float bv = bias[gr];
            #pragma unroll
            for (int nj = 0; nj < 8; nj++) {
                int cn = col0 + wn * 64 + nj * 8 + qid * 2;
                float y0 = sigmoidf_fast(acc[mi][nj][2 * half + 0] + bv);
                float y1 = sigmoidf_fast(acc[mi][nj][2 * half + 1] + bv);
                __half2 hp;
                hp.x = __float2half_rn(y0);
                hp.y = __float2half_rn(y1);
                *reinterpret_cast<__half2*>(y + (long)gr * 1024 + cn) = hp;
            }
        }
    }
}

// ============================================================================
// Output GEMM, single fp16 1-term:
//   out(4096x1024) = A(4096x4160) @ G(4160x1024)
// ============================================================================
__global__ __launch_bounds__(256, 2) void out_mma_kernel(
    const __half* __restrict__ A,
    const __half* __restrict__ Bg,
    float* __restrict__ out)
{
    extern __shared__ char smem[];
    const uint32_t sb = smem_u32(smem);
    const int tid = threadIdx.x;
    const int lane = tid & 31;
    const int wid = tid >> 5;
    const int wm = wid & 3;
    const int wn = wid >> 2;
    const int n0 = blockIdx.y * 128;
    const int col0 = blockIdx.x * 128;

    float acc[2][8][4];
    #pragma unroll
    for (int mi = 0; mi < 2; mi++)
        #pragma unroll
        for (int nj = 0; nj < 8; nj++)
            #pragma unroll
            for (int q = 0; q < 4; q++) acc[mi][nj][q] = 0.0f;

    const int quad = lane >> 3;
    const int r8 = lane & 7;
    const uint32_t aoff = (wm * 32 + (quad & 1) * 8 + r8) * ASTRIDE + (quad >> 1) * 16;
    const uint32_t boff = ((quad & 1) * 8 + r8) * BSTRIDE + (wn * 64 + (quad >> 1) * 8) * 2;

    auto load = [&](int stageIdx, int k0) {
        uint32_t sbase = sb + (uint32_t)stageIdx * STAGE;
        {
            int r = tid >> 1;
            int c = tid & 1;
            long g = (long)(n0 + r) * 4160 + k0 + c * 16;
            cp16(sbase + O_A + r * ASTRIDE + c * 32, A + g);
            cp16(sbase + O_A + r * ASTRIDE + c * 32 + 16, A + g + 8);
        }
        #pragma unroll
        for (int i = 0; i < 2; i++) {
            int idx = tid + i * 256;
            int r = idx >> 4;
            int c = idx & 15;
            long g = (long)(k0 + r) * 1024 + col0 + c * 8;
            cp16(sbase + O_B + r * BSTRIDE + c * 16, Bg + g);
        }
    };

    load(0, 0);
    CP_COMMIT();
    load(1, 32);
    CP_COMMIT();

    int curStage = 0, nxtStage = 2;
    for (int t = 0; t < 130; t++) {
        CP_WAIT(1);
        __syncthreads();
        if (t + 2 < 130) load(nxtStage, (t + 2) * 32);
        CP_COMMIT();

        const uint32_t cur = sb + (uint32_t)curStage * STAGE;
        curStage = (curStage == NSTAGES - 1) ? 0 : curStage + 1;
        nxtStage = (nxtStage == NSTAGES - 1) ? 0 : nxtStage + 1;

        #pragma unroll
        for (int ks = 0; ks < 2; ks++) {
            uint32_t af[2][4];
            ldsm_x4(af[0], cur + O_A + aoff + ks * 32);
            ldsm_x4(af[1], cur + O_A + aoff + 16 * ASTRIDE + ks * 32);

            #pragma unroll
            for (int g = 0; g < 4; g++) {
                uint32_t rh[4];
                ldsm_x4t(rh, cur + O_B + boff + g * 32 + ks * 16 * BSTRIDE);
                mma_f16(acc[0][2 * g],     af[0], &rh[0]);
                mma_f16(acc[0][2 * g + 1], af[0], &rh[2]);
                mma_f16(acc[1][2 * g],     af[1], &rh[0]);
                mma_f16(acc[1][2 * g + 1], af[1], &rh[2]);
            }
        }
        __syncthreads();
    }

    const int grp = lane >> 2;
    const int qid = lane & 3;
    #pragma unroll
    for (int mi = 0; mi < 2; mi++) {
        int rbase = n0 + wm * 32 + mi * 16;
        #pragma unroll
        for (int nj = 0; nj < 8; nj++) {
            int cn = col0 + wn * 64 + nj * 8 + qid * 2;
            *reinterpret_cast<float2*>(&out[(long)(rbase + grp) * 1024 + cn]) =
                make_float2(acc[mi][nj][0], acc[mi][nj][1]);
            *reinterpret_cast<float2*>(&out[(long)(rbase + grp + 8) * 1024 + cn]) =
                make_float2(acc[mi][nj][2], acc[mi][nj][3]);
        }
    }
}

// ============================================================================
// Launch
// ============================================================================
extern "C" void kernel_launch(void* const* d_in, const int* in_sizes, int n_in,
                              void* d_out, int out_size) {
    const float* u  = (const float*)d_in[0];
    const float* w0 = (const float*)d_in[1];
    const float* b0 = (const float*)d_in[2];
    const float* w  = (const float*)d_in[3];
    const float* b  = (const float*)d_in[4];
    const float* wf = (const float*)d_in[5];
    const float* bf = (const float*)d_in[6];
    const float* xi = (const float*)d_in[7];
    float* out = (float*)d_out;

    void* p;
    cudaGetSymbolAddress(&p, g_uT16);  __half* uT16 = (__half*)p;
    cudaGetSymbolAddress(&p, g_W016);  __half* W016 = (__half*)p;
    cudaGetSymbolAddress(&p, g_W16);   __half* W16  = (__half*)p;
    cudaGetSymbolAddress(&p, g_Wf16);  __half* Wf16 = (__half*)p;
    cudaGetSymbolAddress(&p, g_actA16); __half* actA = (__half*)p;
    cudaGetSymbolAddress(&p, g_actB16); __half* actB = (__half*)p;
    cudaGetSymbolAddress(&p, g_A16);   __half* A16 = (__half*)p;
    cudaGetSymbolAddress(&p, g_G16);   __half* G16 = (__half*)p;

    cudaFuncSetAttribute(mlp_mma_kernel,
                         cudaFuncAttributeMaxDynamicSharedMemorySize, SMEM_TOTAL);
    cudaFuncSetAttribute(out_mma_kernel,
                         cudaFuncAttributeMaxDynamicSharedMemorySize, SMEM_TOTAL);

    // ---- precompute ----
    build_A16_kernel<<<4096, 256>>>(xi, A16);
    {
        long c0 = 64L * 256 * 64;
        cvt16_kernel<<<(unsigned)((c0 + 1023) / 1024), 256>>>(w0, W016, c0);
        long c1 = 3L * 64 * 256 * 256;
        cvt16_kernel<<<(unsigned)((c1 + 1023) / 1024), 256>>>(w, W16, c1);
        long c2 = 64L * 65 * 256;
        cvt16_kernel<<<(unsigned)((c2 + 1023) / 1024), 256>>>(wf, Wf16, c2);
    }
    transpose_u16_kernel<<<dim3(32, 2), dim3(32, 32)>>>(u, uT16);

    // ---- MLP chain (fp16 1-term) ----
    mlp_mma_kernel<<<dim3(8, 2, 64), 256, SMEM_TOTAL>>>(
        W016, 256L * 64, uT16, 0L, b0, 256,
        actA, 256L * 1024, 256, 64);

    const __half* src = actA;
    __half* dst = actB;
    for (int i = 0; i < 3; i++) {
        mlp_mma_kernel<<<dim3(8, 2, 64), 256, SMEM_TOTAL>>>(
            W16 + (long)i * 64 * 256 * 256, 256L * 256,
            src, 256L * 1024,
            b + (long)i * 64 * 256, 256,
            dst, 256L * 1024, 256, 256);
        const __half* t = src;
        src = dst;
        dst = (__half*)t;
    }

    // final layer: rows=65 -> G (4160 x 1024) single fp16
    mlp_mma_kernel<<<dim3(8, 1, 64), 256, SMEM_TOTAL>>>(
        Wf16, 65L * 256, src, 256L * 1024, bf, 65,
        G16, 65L * 1024, 65, 256);

    // ---- output GEMM (fp16 1-term) ----
    out_mma_kernel<<<dim3(8, 32), 256, SMEM_TOTAL>>>(A16, G16, out);
}

// round 15
// speedup vs baseline: 1.6271x; 1.6271x over previous
#include <cuda_runtime.h>
#include <cuda_bf16.h>
#include <cuda_fp16.h>
#include <cstdint>

// ============================================================================
// spectralNNDeepshared2 — Round 14:
//   1-term single-fp16 mma.sync (precision validated R13: rel_err 3.1e-4)
//   K-chunk doubled to 64: half the pipeline iterations/syncs of R13,
//   R11-proven coalesced loaders. 3-stage ring, 2 CTAs/SM.
// ============================================================================

// ---------------- scratch ----------------
__device__ __half g_uT16[64 * 1024];
__device__ __half g_W016[64 * 256 * 64];
__device__ __half g_W16[3L * 64 * 256 * 256];
__device__ __half g_Wf16[64 * 65 * 256];
__device__ __half g_actA16[64L * 256 * 1024];
__device__ __half g_actB16[64L * 256 * 1024];
__device__ __half g_A16[4096L * 4160];
__device__ __half g_G16[4160L * 1024];

__device__ __forceinline__ float sigmoidf_fast(float x) {
    return 1.0f / (1.0f + __expf(-x));
}
__device__ __forceinline__ uint32_t smem_u32(const void* p) {
    uint32_t a;
    asm("{ .reg .u64 t; cvta.to.shared.u64 t, %1; cvt.u32.u64 %0, t; }"
        : "=r"(a) : "l"(p));
    return a;
}

// ---------------- cp.async / ldmatrix / mma helpers ----------------
__device__ __forceinline__ void cp16(uint32_t dst, const void* src) {
    asm volatile("cp.async.cg.shared.global [%0], [%1], 16;\n"
                 :: "r"(dst), "l"(src));
}
__device__ __forceinline__ void cp16z(uint32_t dst, const void* src, bool valid) {
    int sz = valid ? 16 : 0;
    asm volatile("cp.async.cg.shared.global [%0], [%1], 16, %2;\n"
                 :: "r"(dst), "l"(src), "r"(sz));
}
#define CP_COMMIT() asm volatile("cp.async.commit_group;\n" ::: "memory")
#define CP_WAIT(n)  asm volatile("cp.async.wait_group %0;\n" :: "n"(n) : "memory")

__device__ __forceinline__ void ldsm_x4(uint32_t* r, uint32_t addr) {
    asm volatile("ldmatrix.sync.aligned.m8n8.x4.shared.b16 {%0,%1,%2,%3}, [%4];"
        : "=r"(r[0]), "=r"(r[1]), "=r"(r[2]), "=r"(r[3]) : "r"(addr));
}
__device__ __forceinline__ void ldsm_x4t(uint32_t* r, uint32_t addr) {
    asm volatile("ldmatrix.sync.aligned.m8n8.x4.trans.shared.b16 {%0,%1,%2,%3}, [%4];"
        : "=r"(r[0]), "=r"(r[1]), "=r"(r[2]), "=r"(r[3]) : "r"(addr));
}
__device__ __forceinline__ void mma_f16(float* d, const uint32_t* a, const uint32_t* b) {
    asm volatile(
        "mma.sync.aligned.m16n8k16.row.col.f32.f16.f16.f32 "
        "{%0,%1,%2,%3}, {%4,%5,%6,%7}, {%8,%9}, {%0,%1,%2,%3};"
        : "+f"(d[0]), "+f"(d[1]), "+f"(d[2]), "+f"(d[3])
        : "r"(a[0]), "r"(a[1]), "r"(a[2]), "r"(a[3]), "r"(b[0]), "r"(b[1]));
}

// ============================================================================
// Precompute kernels
// ============================================================================
__global__ void cvt16_kernel(const float* __restrict__ src,
                             __half* __restrict__ dst, long count)
{
    long i = (long)blockIdx.x * 1024 + threadIdx.x * 4;
    if (i + 3 >= count) {
        for (long k = i; k < count; k++) dst[k] = __float2half_rn(src[k]);
        return;
    }
    float4 v4 = *reinterpret_cast<const float4*>(src + i);
    __half h4[4];
    h4[0] = __float2half_rn(v4.x);
    h4[1] = __float2half_rn(v4.y);
    h4[2] = __float2half_rn(v4.z);
    h4[3] = __float2half_rn(v4.w);
    *reinterpret_cast<uint2*>(dst + i) = *reinterpret_cast<uint2*>(h4);
}

__global__ void transpose_u16_kernel(const float* __restrict__ u,
                                     __half* __restrict__ uT)
{
    __shared__ float t[32][33];
    int b0 = blockIdx.x * 32;
    int d0 = blockIdx.y * 32;
    int x = threadIdx.x, y = threadIdx.y;
    t[y][x] = u[(long)(b0 + y) * 64 + (d0 + x)];
    __syncthreads();
    uT[(long)(d0 + y) * 1024 + (b0 + x)] = __float2half_rn(t[x][y]);
}

__global__ void build_A16_kernel(const float* __restrict__ xi,
                                 __half* __restrict__ A)
{
    int n = blockIdx.x;
    for (int k = threadIdx.x; k < 4160; k += 256) {
        int m = k / 65;
        int j = k - m * 65;
        A[(long)n * 4160 + k] = __float2half_rn(xi[m * 4160 + n + j]);
    }
}

// ============================================================================
// Shared smem layout: A (128 x 64) + B (64 x 128), single fp16, K-chunk 64,
// 3-stage ring. Strides ≡ 16 (mod 128) -> conflict-free ldmatrix.
// ============================================================================
#define KC 64
#define ASTRIDE 144
#define BSTRIDE 272
#define A_TILE  (128 * ASTRIDE)             // 18432
#define B_TILE  (64 * BSTRIDE)              // 17408
#define STAGE   (A_TILE + B_TILE)           // 35840
#define NSTAGES 3
#define SMEM_TOTAL (NSTAGES * STAGE)        // 107520 (2 CTAs/SM: 210 KB)
#define O_A 0
#define O_B A_TILE

// ============================================================================
// MLP layer: Y[m] = sigmoid(W[m] (rows x K) @ X[m] (K x 1024) + bias[m])
// ============================================================================
__global__ __launch_bounds__(256, 2) void mlp_mma_kernel(
    const __half* __restrict__ W, long wStride,
    const __half* __restrict__ X, long xStride,
    const float* __restrict__ bias_all, int biasStride,
    __half* __restrict__ Y, long yStride,
    int rows, int K)
{
    extern __shared__ char smem[];
    const uint32_t sb = smem_u32(smem);
    const int tid = threadIdx.x;
    const int lane = tid & 31;
    const int wid = tid >> 5;
    const int wm = wid & 3;
    const int wn = wid >> 2;
    const int m = blockIdx.z;
    const int row0 = blockIdx.y * 128;
    const int col0 = blockIdx.x * 128;

    const __half* Aw = W + (long)m * wStride;
    const __half* Bx = X + (long)m * xStride;
    const float* bias = bias_all + (long)m * biasStride;

    float acc[2][8][4];
    #pragma unroll
    for (int mi = 0; mi < 2; mi++)
        #pragma unroll
        for (int nj = 0; nj < 8; nj++)
            #pragma unroll
            for (int q = 0; q < 4; q++) acc[mi][nj][q] = 0.0f;

    const int quad = lane >> 3;
    const int r8 = lane & 7;
    const uint32_t aoff = (wm * 32 + (quad & 1) * 8 + r8) * ASTRIDE + (quad >> 1) * 16;
    const uint32_t boff = ((quad & 1) * 8 + r8) * BSTRIDE + (wn * 64 + (quad >> 1) * 8) * 2;

    const int nChunks = K >> 6;   // K-chunk 64

    auto load = [&](int stageIdx, int k0) {
        uint32_t sbase = sb + (uint32_t)stageIdx * STAGE;
        // A: 128 rows x 8 chunks (16B) = 1024
        #pragma unroll
        for (int i = 0; i < 4; i++) {
            int idx = tid + i * 256;
            int r = idx >> 3;
            int c = idx & 7;
            int gr = row0 + r;
            bool ok = gr < rows;
            long g = (long)(ok ? gr : 0) * K + k0 + c * 8;
            cp16z(sbase + O_A + r * ASTRIDE + c * 16, Aw + g, ok);
        }
        // B: 64 rows x 16 chunks = 1024
        #pragma unroll
        for (int i = 0; i < 4; i++) {
            int idx = tid + i * 256;
            int r = idx >> 4;
            int c = idx & 15;
            long g = (long)(k0 + r) * 1024 + col0 + c * 8;
            cp16(sbase + O_B + r * BSTRIDE + c * 16, Bx + g);
        }
    };

    load(0, 0);
    CP_COMMIT();
    if (nChunks > 1) load(1, KC);
    CP_COMMIT();

    int curStage = 0, nxtStage = 2;
    for (int t = 0; t < nChunks; t++) {
        CP_WAIT(1);
        __syncthreads();
        if (t + 2 < nChunks) load(nxtStage, (t + 2) * KC);
        CP_COMMIT();

        const uint32_t cur = sb + (uint32_t)curStage * STAGE;
        curStage = (curStage == NSTAGES - 1) ? 0 : curStage + 1;
        nxtStage = (nxtStage == NSTAGES - 1) ? 0 : nxtStage + 1;

        #pragma unroll
        for (int ks = 0; ks < 4; ks++) {
            uint32_t af[2][4];
            ldsm_x4(af[0], cur + O_A + aoff + ks * 32);
            ldsm_x4(af[1], cur + O_A + aoff + 16 * ASTRIDE + ks * 32);

            #pragma unroll
            for (int g = 0; g < 4; g++) {
                uint32_t rh[4];
                ldsm_x4t(rh, cur + O_B + boff + g * 32 + ks * 16 * BSTRIDE);
                mma_f16(acc[0][2 * g],     af[0], &rh[0]);
                mma_f16(acc[0][2 * g + 1], af[0], &rh[2]);
                mma_f16(acc[1][2 * g],     af[1], &rh[0]);
                mma_f16(acc[1][2 * g + 1], af[1], &rh[2]);
            }
        }
        __syncthreads();
    }

    // epilogue: bias + sigmoid -> single fp16
    const int grp = lane >> 2;
    const int qid = lane & 3;
    __half* y = Y + (long)m * yStride;
    #pragma unroll
    for (int mi = 0; mi < 2; mi++) {
        int rbase = row0 + wm * 32 + mi * 16;
        #pragma unroll
        for (int half = 0; half < 2; half++) {
            int gr = rbase + grp + half * 8;
            if (gr >= rows) continue;
            float bv = bias[gr];
            #pragma unroll
            for (int nj = 0; nj < 8; nj++) {
                int cn = col0 + wn * 64 + nj * 8 + qid * 2;
                float y0 = sigmoidf_fast(acc[mi][nj][2 * half + 0] + bv);
                float y1 = sigmoidf_fast(acc[mi][nj][2 * half + 1] + bv);
                __half2 hp;
                hp.x = __float2half_rn(y0);
                hp.y = __float2half_rn(y1);
                *reinterpret_cast<__half2*>(y + (long)gr * 1024 + cn) = hp;
            }
        }
    }
}

// ============================================================================
// Output GEMM: out(4096x1024) = A(4096x4160) @ G(4160x1024), K-chunk 64
// ============================================================================
__global__ __launch_bounds__(256, 2) void out_mma_kernel(
    const __half* __restrict__ A,
    const __half* __restrict__ Bg,
    float* __restrict__ out)
{
    extern __shared__ char smem[];
    const uint32_t sb = smem_u32(smem);
    const int tid = threadIdx.x;
    const int lane = tid & 31;
    const int wid = tid >> 5;
    const int wm = wid & 3;
    const int wn = wid >> 2;
    const int n0 = blockIdx.y * 128;
    const int col0 = blockIdx.x * 128;

    float acc[2][8][4];
    #pragma unroll
    for (int mi = 0; mi < 2; mi++)
        #pragma unroll
        for (int nj = 0; nj < 8; nj++)
            #pragma unroll
            for (int q = 0; q < 4; q++) acc[mi][nj][q] = 0.0f;

    const int quad = lane >> 3;
    const int r8 = lane & 7;
    const uint32_t aoff = (wm * 32 + (quad & 1) * 8 + r8) * ASTRIDE + (quad >> 1) * 16;
    const uint32_t boff = ((quad & 1) * 8 + r8) * BSTRIDE + (wn * 64 + (quad >> 1) * 8) * 2;

    auto load = [&](int stageIdx, int k0) {
        uint32_t sbase = sb + (uint32_t)stageIdx * STAGE;
        #pragma unroll
        for (int i = 0; i < 4; i++) {
            int idx = tid + i * 256;
            int r = idx >> 3;
            int c = idx & 7;
            long g = (long)(n0 + r) * 4160 + k0 + c * 8;
            cp16(sbase + O_A + r * ASTRIDE + c * 16, A + g);
        }
        #pragma unroll
        for (int i = 0; i < 4; i++) {
            int idx = tid + i * 256;
            int r = idx >> 4;
            int c = idx & 15;
            long g = (long)(k0 + r) * 1024 + col0 + c * 8;
            cp16(sbase + O_B + r * BSTRIDE + c * 16, Bg + g);
        }
    };

    load(0, 0);
    CP_COMMIT();
    load(1, KC);
    CP_COMMIT();

    int curStage = 0, nxtStage = 2;
    for (int t = 0; t < 65; t++) {
        CP_WAIT(1);
        __syncthreads();
        if (t + 2 < 65) load(nxtStage, (t + 2) * KC);
        CP_COMMIT();

        const uint32_t cur = sb + (uint32_t)curStage * STAGE;
        curStage = (curStage == NSTAGES - 1) ? 0 : curStage + 1;
        nxtStage = (nxtStage == NSTAGES - 1) ? 0 : nxtStage + 1;

        #pragma unroll
        for (int ks = 0; ks < 4; ks++) {
            uint32_t af[2][4];
            ldsm_x4(af[0], cur + O_A + aoff + ks * 32);
            ldsm_x4(af[1], cur + O_A + aoff + 16 * ASTRIDE + ks * 32);

            #pragma unroll
            for (int g = 0; g < 4; g++) {
                uint32_t rh[4];
                ldsm_x4t(rh, cur + O_B + boff + g * 32 + ks * 16 * BSTRIDE);
                mma_f16(acc[0][2 * g],     af[0], &rh[0]);
                mma_f16(acc[0][2 * g + 1], af[0], &rh[2]);
                mma_f16(acc[1][2 * g],     af[1], &rh[0]);
                mma_f16(acc[1][2 * g + 1], af[1], &rh[2]);
            }
        }
        __syncthreads();
    }

    const int grp = lane >> 2;
    const int qid = lane & 3;
    #pragma unroll
    for (int mi = 0; mi < 2; mi++) {
        int rbase = n0 + wm * 32 + mi * 16;
        #pragma unroll
        for (int nj = 0; nj < 8; nj++) {
            int cn = col0 + wn * 64 + nj * 8 + qid * 2;
            *reinterpret_cast<float2*>(&out[(long)(rbase + grp) * 1024 + cn]) =
                make_float2(acc[mi][nj][0], acc[mi][nj][1]);
            *reinterpret_cast<float2*>(&out[(long)(rbase + grp + 8) * 1024 + cn]) =
                make_float2(acc[mi][nj][2], acc[mi][nj][3]);
        }
    }
}

// ============================================================================
// Launch
// ============================================================================
extern "C" void kernel_launch(void* const* d_in, const int* in_sizes, int n_in,
                              void* d_out, int out_size) {
    const float* u  = (const float*)d_in[0];
    const float* w0 = (const float*)d_in[1];
    const float* b0 = (const float*)d_in[2];
    const float* w  = (const float*)d_in[3];
    const float* b  = (const float*)d_in[4];
    const float* wf = (const float*)d_in[5];
    const float* bf = (const float*)d_in[6];
    const float* xi = (const float*)d_in[7];
    float* out = (float*)d_out;

    void* p;
    cudaGetSymbolAddress(&p, g_uT16);  __half* uT16 = (__half*)p;
    cudaGetSymbolAddress(&p, g_W016);  __half* W016 = (__half*)p;
    cudaGetSymbolAddress(&p, g_W16);   __half* W16  = (__half*)p;
    cudaGetSymbolAddress(&p, g_Wf16);  __half* Wf16 = (__half*)p;
    cudaGetSymbolAddress(&p, g_actA16); __half* actA = (__half*)p;
    cudaGetSymbolAddress(&p, g_actB16); __half* actB = (__half*)p;
    cudaGetSymbolAddress(&p, g_A16);   __half* A16 = (__half*)p;
    cudaGetSymbolAddress(&p, g_G16);   __half* G16 = (__half*)p;

    cudaFuncSetAttribute(mlp_mma_kernel,
                         cudaFuncAttributeMaxDynamicSharedMemorySize, SMEM_TOTAL);
    cudaFuncSetAttribute(out_mma_kernel,
                         cudaFuncAttributeMaxDynamicSharedMemorySize, SMEM_TOTAL);

    // ---- precompute ----
    build_A16_kernel<<<4096, 256>>>(xi, A16);
    {
        long c0 = 64L * 256 * 64;
        cvt16_kernel<<<(unsigned)((c0 + 1023) / 1024), 256>>>(w0, W016, c0);
        long c1 = 3L * 64 * 256 * 256;
        cvt16_kernel<<<(unsigned)((c1 + 1023) / 1024), 256>>>(w, W16, c1);
        long c2 = 64L * 65 * 256;
        cvt16_kernel<<<(unsigned)((c2 + 1023) / 1024), 256>>>(wf, Wf16, c2);
    }
    transpose_u16_kernel<<<dim3(32, 2), dim3(32, 32)>>>(u, uT16);

    // ---- MLP chain (fp16 1-term, K-chunk 64) ----
    mlp_mma_kernel<<<dim3(8, 2, 64), 256, SMEM_TOTAL>>>(
        W016, 256L * 64, uT16, 0L, b0, 256,
        actA, 256L * 1024, 256, 64);

    const __half* src = actA;
    __half* dst = actB;
    for (int i = 0; i < 3; i++) {
        mlp_mma_kernel<<<dim3(8, 2, 64), 256, SMEM_TOTAL>>>(
            W16 + (long)i * 64 * 256 * 256, 256L * 256,
            src, 256L * 1024,
            b + (long)i * 64 * 256, 256,
            dst, 256L * 1024, 256, 256);
        const __half* t = src;
        src = dst;
        dst = (__half*)t;
    }

    // final layer: rows=65 -> G (4160 x 1024) single fp16
    mlp_mma_kernel<<<dim3(8, 1, 64), 256, SMEM_TOTAL>>>(
        Wf16, 65L * 256, src, 256L * 1024, bf, 65,
        G16, 65L * 1024, 65, 256);

    // ---- output GEMM (fp16 1-term, K-chunk 64) ----
    out_mma_kernel<<<dim3(8, 32), 256, SMEM_TOTAL>>>(A16, G16, out);
}

// round 17
// speedup vs baseline: 1.7113x; 1.0518x over previous
#include <cuda_runtime.h>
#include <cuda_bf16.h>
#include <cuda_fp16.h>
#include <cstdint>

// ============================================================================
// spectralNNDeepshared2 — Round 16 (R15 resubmit; container infra failure):
//   R14 winner (1-term fp16, K-chunk 64, 3-stage ring) + overhead trims:
//     - single __syncthreads per chunk (trailing sync proven redundant)
//     - vectorized build_A16 (8B stores)
//     - fused weight-convert kernel (1 launch instead of 3)
// ============================================================================

// ---------------- scratch ----------------
__device__ __half g_uT16[64 * 1024];
__device__ __half g_W016[64 * 256 * 64];
__device__ __half g_W16[3L * 64 * 256 * 256];
__device__ __half g_Wf16[64 * 65 * 256];
__device__ __half g_actA16[64L * 256 * 1024];
__device__ __half g_actB16[64L * 256 * 1024];
__device__ __half g_A16[4096L * 4160];
__device__ __half g_G16[4160L * 1024];

__device__ __forceinline__ float sigmoidf_fast(float x) {
    return 1.0f / (1.0f + __expf(-x));
}
__device__ __forceinline__ uint32_t smem_u32(const void* p) {
    uint32_t a;
    asm("{ .reg .u64 t; cvta.to.shared.u64 t, %1; cvt.u32.u64 %0, t; }"
        : "=r"(a) : "l"(p));
    return a;
}

// ---------------- cp.async / ldmatrix / mma helpers ----------------
__device__ __forceinline__ void cp16(uint32_t dst, const void* src) {
    asm volatile("cp.async.cg.shared.global [%0], [%1], 16;\n"
                 :: "r"(dst), "l"(src));
}
__device__ __forceinline__ void cp16z(uint32_t dst, const void* src, bool valid) {
    int sz = valid ? 16 : 0;
    asm volatile("cp.async.cg.shared.global [%0], [%1], 16, %2;\n"
                 :: "r"(dst), "l"(src), "r"(sz));
}
#define CP_COMMIT() asm volatile("cp.async.commit_group;\n" ::: "memory")
#define CP_WAIT(n)  asm volatile("cp.async.wait_group %0;\n" :: "n"(n) : "memory")

__device__ __forceinline__ void ldsm_x4(uint32_t* r, uint32_t addr) {
    asm volatile("ldmatrix.sync.aligned.m8n8.x4.shared.b16 {%0,%1,%2,%3}, [%4];"
        : "=r"(r[0]), "=r"(r[1]), "=r"(r[2]), "=r"(r[3]) : "r"(addr));
}
__device__ __forceinline__ void ldsm_x4t(uint32_t* r, uint32_t addr) {
    asm volatile("ldmatrix.sync.aligned.m8n8.x4.trans.shared.b16 {%0,%1,%2,%3}, [%4];"
        : "=r"(r[0]), "=r"(r[1]), "=r"(r[2]), "=r"(r[3]) : "r"(addr));
}
__device__ __forceinline__ void mma_f16(float* d, const uint32_t* a, const uint32_t* b) {
    asm volatile(
        "mma.sync.aligned.m16n8k16.row.col.f32.f16.f16.f32 "
        "{%0,%1,%2,%3}, {%4,%5,%6,%7}, {%8,%9}, {%0,%1,%2,%3};"
        : "+f"(d[0]), "+f"(d[1]), "+f"(d[2]), "+f"(d[3])
        : "r"(a[0]), "r"(a[1]), "r"(a[2]), "r"(a[3]), "r"(b[0]), "r"(b[1]));
}

// ============================================================================
// Precompute kernels
// ============================================================================
__global__ void cvt16_all_kernel(
    const float* __restrict__ s0, __half* __restrict__ d0, long c0,
    const float* __restrict__ s1, __half* __restrict__ d1, long c1,
    const float* __restrict__ s2, __half* __restrict__ d2, long c2)
{
    long i = (long)blockIdx.x * 1024 + threadIdx.x * 4;
    const float* src;
    __half* dst;
    long count;
    if (i < c0) { src = s0; dst = d0; count = c0; }
    else if (i < c0 + c1) { i -= c0; src = s1; dst = d1; count = c1; }
    else { i -= c0 + c1; src = s2; dst = d2; count = c2; }
    if (i >= count) return;
    if (i + 3 >= count) {
        for (long k = i; k < count; k++) dst[k] = __float2half_rn(src[k]);
        return;
    }
    float4 v4 = *reinterpret_cast<const float4*>(src + i);
    __half h4[4];
    h4[0] = __float2half_rn(v4.x);
    h4[1] = __float2half_rn(v4.y);
    h4[2] = __float2half_rn(v4.z);
    h4[3] = __float2half_rn(v4.w);
    *reinterpret_cast<uint2*>(dst + i) = *reinterpret_cast<uint2*>(h4);
}

__global__ void transpose_u16_kernel(const float* __restrict__ u,
                                     __half* __restrict__ uT)
{
    __shared__ float t[32][33];
    int b0 = blockIdx.x * 32;
    int d0 = blockIdx.y * 32;
    int x = threadIdx.x, y = threadIdx.y;
    t[y][x] = u[(long)(b0 + y) * 64 + (d0 + x)];
    __syncthreads();
    uT[(long)(d0 + y) * 1024 + (b0 + x)] = __float2half_rn(t[x][y]);
}

__global__ void build_A16_kernel(const float* __restrict__ xi,
                                 __half* __restrict__ A)
{
    int n = blockIdx.x;
    for (int kg = threadIdx.x; kg < 1040; kg += 256) {
        int k = kg * 4;
        __half h4[4];
        #pragma unroll
        for (int e = 0; e < 4; e++) {
            int kk = k + e;
            int m = kk / 65;
            int j = kk - m * 65;
            h4[e] = __float2half_rn(xi[m * 4160 + n + j]);
        }
        *reinterpret_cast<uint2*>(A + (long)n * 4160 + k) =
            *reinterpret_cast<uint2*>(h4);
    }
}

// ============================================================================
// Shared smem layout: A (128 x 64) + B (64 x 128), single fp16, K-chunk 64,
// 3-stage ring. Strides ≡ 16 (mod 128) -> conflict-free ldmatrix.
// ============================================================================
#define KC 64
#define ASTRIDE 144
#define BSTRIDE 272
#define A_TILE  (128 * ASTRIDE)             // 18432
#define B_TILE  (64 * BSTRIDE)              // 17408
#define STAGE   (A_TILE + B_TILE)           // 35840
#define NSTAGES 3
#define SMEM_TOTAL (NSTAGES * STAGE)        // 107520 (2 CTAs/SM: 210 KB)
#define O_A 0
#define O_B A_TILE

// ============================================================================
// MLP layer: Y[m] = sigmoid(W[m] (rows x K) @ X[m] (K x 1024) + bias[m])
// Single-sync-per-chunk pipeline.
// ============================================================================
__global__ __launch_bounds__(256, 2) void mlp_mma_kernel(
    const __half* __restrict__ W, long wStride,
    const __half* __restrict__ X, long xStride,
    const float* __restrict__ bias_all, int biasStride,
    __half* __restrict__ Y, long yStride,
    int rows, int K)
{
    extern __shared__ char smem[];
    const uint32_t sb = smem_u32(smem);
    const int tid = threadIdx.x;
    const int lane = tid & 31;
    const int wid = tid >> 5;
    const int wm = wid & 3;
    const int wn = wid >> 2;
    const int m = blockIdx.z;
    const int row0 = blockIdx.y * 128;
    const int col0 = blockIdx.x * 128;

    const __half* Aw = W + (long)m * wStride;
    const __half* Bx = X + (long)m * xStride;
    const float* bias = bias_all + (long)m * biasStride;

    float acc[2][8][4];
    #pragma unroll
    for (int mi = 0; mi < 2; mi++)
        #pragma unroll
        for (int nj = 0; nj < 8; nj++)
            #pragma unroll
            for (int q = 0; q < 4; q++) acc[mi][nj][q] = 0.0f;

    const int quad = lane >> 3;
    const int r8 = lane & 7;
    const uint32_t aoff = (wm * 32 + (quad & 1) * 8 + r8) * ASTRIDE + (quad >> 1) * 16;
    const uint32_t boff = ((quad & 1) * 8 + r8) * BSTRIDE + (wn * 64 + (quad >> 1) * 8) * 2;

    const int nChunks = K >> 6;

    auto load = [&](int stageIdx, int k0) {
        uint32_t sbase = sb + (uint32_t)stageIdx * STAGE;
        #pragma unroll
        for (int i = 0; i < 4; i++) {
            int idx = tid + i * 256;
            int r = idx >> 3;
            int c = idx & 7;
            int gr = row0 + r;
            bool ok = gr < rows;
            long g = (long)(ok ? gr : 0) * K + k0 + c * 8;
            cp16z(sbase + O_A + r * ASTRIDE + c * 16, Aw + g, ok);
        }
        #pragma unroll
        for (int i = 0; i < 4; i++) {
            int idx = tid + i * 256;
            int r = idx >> 4;
            int c = idx & 15;
            long g = (long)(k0 + r) * 1024 + col0 + c * 8;
            cp16(sbase + O_B + r * BSTRIDE + c * 16, Bx + g);
        }
    };

    load(0, 0);
    CP_COMMIT();
    if (nChunks > 1) load(1, KC);
    CP_COMMIT();

    int curStage = 0, nxtStage = 2;
    for (int t = 0; t < nChunks; t++) {
        CP_WAIT(1);
        __syncthreads();   // orders stage-t visibility AND protects stage reuse
        if (t + 2 < nChunks) load(nxtStage, (t + 2) * KC);
        CP_COMMIT();

        const uint32_t cur = sb + (uint32_t)curStage * STAGE;
        curStage = (curStage == NSTAGES - 1) ? 0 : curStage + 1;
        nxtStage = (nxtStage == NSTAGES - 1) ? 0 : nxtStage + 1;

        #pragma unroll
        for (int ks = 0; ks < 4; ks++) {
            uint32_t af[2][4];
            ldsm_x4(af[0], cur + O_A + aoff + ks * 32);
            ldsm_x4(af[1], cur + O_A + aoff + 16 * ASTRIDE + ks * 32);

            #pragma unroll
            for (int g = 0; g < 4; g++) {
                uint32_t rh[4];
                ldsm_x4t(rh, cur + O_B + boff + g * 32 + ks * 16 * BSTRIDE);
                mma_f16(acc[0][2 * g],     af[0], &rh[0]);
                mma_f16(acc[0][2 * g + 1], af[0], &rh[2]);
                mma_f16(acc[1][2 * g],     af[1], &rh[0]);
                mma_f16(acc[1][2 * g + 1], af[1], &rh[2]);
            }
        }
        // no trailing sync: top-of-iteration sync already orders reuse
    }

    // epilogue: bias + sigmoid -> single fp16
    const int grp = lane >> 2;
    const int qid = lane & 3;
    __half* y = Y + (long)m * yStride;
    #pragma unroll
    for (int mi = 0; mi < 2; mi++) {
        int rbase = row0 + wm * 32 + mi * 16;
        #pragma unroll
        for (int half = 0; half < 2; half++) {
            int gr = rbase + grp + half * 8;
            if (gr >= rows) continue;
            float bv = bias[gr];
            #pragma unroll
            for (int nj = 0; nj < 8; nj++) {
                int cn = col0 + wn * 64 + nj * 8 + qid * 2;
                float y0 = sigmoidf_fast(acc[mi][nj][2 * half + 0] + bv);
                float y1 = sigmoidf_fast(acc[mi][nj][2 * half + 1] + bv);
                __half2 hp;
                hp.x = __float2half_rn(y0);
                hp.y = __float2half_rn(y1);
                *reinterpret_cast<__half2*>(y + (long)gr * 1024 + cn) = hp;
            }
        }
    }
}

// ============================================================================
// Output GEMM: out(4096x1024) = A(4096x4160) @ G(4160x1024), K-chunk 64
// Single-sync-per-chunk pipeline.
// ============================================================================
__global__ __launch_bounds__(256, 2) void out_mma_kernel(
    const __half* __restrict__ A,
    const __half* __restrict__ Bg,
    float* __restrict__ out)
{
    extern __shared__ char smem[];
    const uint32_t sb = smem_u32(smem);
    const int tid = threadIdx.x;
    const int lane = tid & 31;
    const int wid = tid >> 5;
    const int wm = wid & 3;
    const int wn = wid >> 2;
    const int n0 = blockIdx.y * 128;
    const int col0 = blockIdx.x * 128;

    float acc[2][8][4];
    #pragma unroll
    for (int mi = 0; mi < 2; mi++)
        #pragma unroll
        for (int nj = 0; nj < 8; nj++)
            #pragma unroll
            for (int q = 0; q < 4; q++) acc[mi][nj][q] = 0.0f;

    const int quad = lane >> 3;
    const int r8 = lane & 7;
    const uint32_t aoff = (wm * 32 + (quad & 1) * 8 + r8) * ASTRIDE + (quad >> 1) * 16;
    const uint32_t boff = ((quad & 1) * 8 + r8) * BSTRIDE + (wn * 64 + (quad >> 1) * 8) * 2;

    auto load = [&](int stageIdx, int k0) {
        uint32_t sbase = sb + (uint32_t)stageIdx * STAGE;
        #pragma unroll
        for (int i = 0; i < 4; i++) {
            int idx = tid + i * 256;
            int r = idx >> 3;
            int c = idx & 7;
            long g = (long)(n0 + r) * 4160 + k0 + c * 8;
            cp16(sbase + O_A + r * ASTRIDE + c * 16, A + g);
        }
        #pragma unroll
        for (int i = 0; i < 4; i++) {
            int idx = tid + i * 256;
            int r = idx >> 4;
            int c = idx & 15;
            long g = (long)(k0 + r) * 1024 + col0 + c * 8;
            cp16(sbase + O_B + r * BSTRIDE + c * 16, Bg + g);
        }
    };

    load(0, 0);
    CP_COMMIT();
    load(1, KC);
    CP_COMMIT();

    int curStage = 0, nxtStage = 2;
    for (int t = 0; t < 65; t++) {
        CP_WAIT(1);
        __syncthreads();
        if (t + 2 < 65) load(nxtStage, (t + 2) * KC);
        CP_COMMIT();

        const uint32_t cur = sb + (uint32_t)curStage * STAGE;
        curStage = (curStage == NSTAGES - 1) ? 0 : curStage + 1;
        nxtStage = (nxtStage == NSTAGES - 1) ? 0 : nxtStage + 1;

        #pragma unroll
        for (int ks = 0; ks < 4; ks++) {
            uint32_t af[2][4];
            ldsm_x4(af[0], cur + O_A + aoff + ks * 32);
            ldsm_x4(af[1], cur + O_A + aoff + 16 * ASTRIDE + ks * 32);

            #pragma unroll
            for (int g = 0; g < 4; g++) {
                uint32_t rh[4];
                ldsm_x4t(rh, cur + O_B + boff + g * 32 + ks * 16 * BSTRIDE);
                mma_f16(acc[0][2 * g],     af[0], &rh[0]);
                mma_f16(acc[0][2 * g + 1], af[0], &rh[2]);
                mma_f16(acc[1][2 * g],     af[1], &rh[0]);
                mma_f16(acc[1][2 * g + 1], af[1], &rh[2]);
            }
        }
    }

    const int grp = lane >> 2;
    const int qid = lane & 3;
    #pragma unroll
    for (int mi = 0; mi < 2; mi++) {
        int rbase = n0 + wm * 32 + mi * 16;
        #pragma unroll
        for (int nj = 0; nj < 8; nj++) {
            int cn = col0 + wn * 64 + nj * 8 + qid * 2;
            *reinterpret_cast<float2*>(&out[(long)(rbase + grp) * 1024 + cn]) =
                make_float2(acc[mi][nj][0], acc[mi][nj][1]);
            *reinterpret_cast<float2*>(&out[(long)(rbase + grp + 8) * 1024 + cn]) =
                make_float2(acc[mi][nj][2], acc[mi][nj][3]);
        }
    }
}

// ============================================================================
// Launch
// ============================================================================
extern "C" void kernel_launch(void* const* d_in, const int* in_sizes, int n_in,
                              void* d_out, int out_size) {
    const float* u  = (const float*)d_in[0];
    const float* w0 = (const float*)d_in[1];
    const float* b0 = (const float*)d_in[2];
    const float* w  = (const float*)d_in[3];
    const float* b  = (const float*)d_in[4];
    const float* wf = (const float*)d_in[5];
    const float* bf = (const float*)d_in[6];
    const float* xi = (const float*)d_in[7];
    float* out = (float*)d_out;

    void* p;
    cudaGetSymbolAddress(&p, g_uT16);  __half* uT16 = (__half*)p;
    cudaGetSymbolAddress(&p, g_W016);  __half* W016 = (__half*)p;
    cudaGetSymbolAddress(&p, g_W16);   __half* W16  = (__half*)p;
    cudaGetSymbolAddress(&p, g_Wf16);  __half* Wf16 = (__half*)p;
    cudaGetSymbolAddress(&p, g_actA16); __half* actA = (__half*)p;
    cudaGetSymbolAddress(&p, g_actB16); __half* actB = (__half*)p;
    cudaGetSymbolAddress(&p, g_A16);   __half* A16 = (__half*)p;
    cudaGetSymbolAddress(&p, g_G16);   __half* G16 = (__half*)p;

    cudaFuncSetAttribute(mlp_mma_kernel,
                         cudaFuncAttributeMaxDynamicSharedMemorySize, SMEM_TOTAL);
    cudaFuncSetAttribute(out_mma_kernel,
                         cudaFuncAttributeMaxDynamicSharedMemorySize, SMEM_TOTAL);

    // ---- precompute ----
    build_A16_kernel<<<4096, 256>>>(xi, A16);
    {
        long c0 = 64L * 256 * 64;
        long c1 = 3L * 64 * 256 * 256;
        long c2 = 64L * 65 * 256;
        long total = c0 + c1 + c2;
        cvt16_all_kernel<<<(unsigned)((total + 1023) / 1024), 256>>>(
            w0, W016, c0, w, W16, c1, wf, Wf16, c2);
    }
    transpose_u16_kernel<<<dim3(32, 2), dim3(32, 32)>>>(u, uT16);

    // ---- MLP chain (fp16 1-term, K-chunk 64) ----
    mlp_mma_kernel<<<dim3(8, 2, 64), 256, SMEM_TOTAL>>>(
        W016, 256L * 64, uT16, 0L, b0, 256,
        actA, 256L * 1024, 256, 64);

    const __half* src = actA;
    __half* dst = actB;
    for (int i = 0; i < 3; i++) {
        mlp_mma_kernel<<<dim3(8, 2, 64), 256, SMEM_TOTAL>>>(
            W16 + (long)i * 64 * 256 * 256, 256L * 256,
            src, 256L * 1024,
            b + (long)i * 64 * 256, 256,
            dst, 256L * 1024, 256, 256);
        const __half* t = src;
        src = dst;
        dst = (__half*)t;
    }

    // final layer: rows=65 -> G (4160 x 1024) single fp16
    mlp_mma_kernel<<<dim3(8, 1, 64), 256, SMEM_TOTAL>>>(
        Wf16, 65L * 256, src, 256L * 1024, bf, 65,
        G16, 65L * 1024, 65, 256);

    // ---- output GEMM (fp16 1-term, K-chunk 64) ----
    out_mma_kernel<<<dim3(8, 32), 256, SMEM_TOTAL>>>(A16, G16, out);
}